// round 7
// baseline (speedup 1.0000x reference)
#include <cuda_runtime.h>
#include <cuda_fp16.h>
#include <cstdint>

// Problem constants (fixed by the dataset)
#define NN   50000
#define EE   1600000
#define EN   1650000      // EE + NN self loops
#define IND  256
#define HID  256
#define OUTD 48
#define KHOP 10
#define NBS  196          // ceil(NN/256) scan blocks

typedef unsigned long long u64;

// Packed fp32x2 FMA: d = a*b + d (elementwise on 2 packed floats)
#define FMA2(acc, a, b) \
    asm("fma.rn.f32x2 %0, %1, %2, %0;" : "+l"(acc) : "l"(a), "l"(b))
#define PACK_DUP(out, f) do { \
    unsigned _u = __float_as_uint(f); \
    asm("mov.b64 %0, {%1, %1};" : "=l"(out) : "r"(_u)); \
} while (0)
#define UNPACK2(lo, hi, in) \
    asm("mov.b64 {%0, %1}, %2;" : "=r"(lo), "=r"(hi) : "l"(in))

// ---------------- scratch (device globals; no allocation allowed) ----------
__device__ float     g_relu[NN * HID];    // relu(x@W1+b1)
__device__ float     g_h[NN * OUTD];      // MLP output h (fp32)
__device__ uint4     g_rf0[NN * 6];       // fp16 r ping (48 halves per node)
__device__ uint4     g_rf1[NN * 6];       // fp16 r pong
__device__ int       g_deg[NN];
__device__ int       g_scan[NN];
__device__ int       g_bsum[256];
__device__ int       g_boff[256];
__device__ int       g_rowptr[NN + 1];
__device__ int       g_cursor[NN];
__device__ float     g_dinv[NN];
__device__ long long g_edges[EN];         // packed {src:int32 (lo), norm:f32 (hi)}

// ---------------- CSR build -------------------------------------------------
__global__ void k_init_deg() {
    int i = blockIdx.x * blockDim.x + threadIdx.x;
    if (i < NN) g_deg[i] = 1;   // self loop
}

__global__ void k_count(const int* __restrict__ ei) {
    int i = blockIdx.x * blockDim.x + threadIdx.x;
    if (i < EE) {
        int d = ei[EE + i];
        if ((unsigned)d < NN) atomicAdd(&g_deg[d], 1);
    }
}

__global__ void k_scan1() {
    __shared__ int s[256];
    int tx = threadIdx.x;
    int i = blockIdx.x * 256 + tx;
    int v = (i < NN) ? g_deg[i] : 0;
    s[tx] = v;
    __syncthreads();
    #pragma unroll
    for (int off = 1; off < 256; off <<= 1) {
        int add = (tx >= off) ? s[tx - off] : 0;
        __syncthreads();
        s[tx] += add;
        __syncthreads();
    }
    if (i < NN) g_scan[i] = s[tx];
    if (tx == 255) g_bsum[blockIdx.x] = s[255];
}

__global__ void k_scan2() {
    __shared__ int s[256];
    int tx = threadIdx.x;
    int v = (tx < NBS) ? g_bsum[tx] : 0;
    s[tx] = v;
    __syncthreads();
    #pragma unroll
    for (int off = 1; off < 256; off <<= 1) {
        int add = (tx >= off) ? s[tx - off] : 0;
        __syncthreads();
        s[tx] += add;
        __syncthreads();
    }
    g_boff[tx] = s[tx] - v;   // exclusive
}

__global__ void k_scan3() {
    int i = blockIdx.x * blockDim.x + threadIdx.x;
    if (i >= NN) return;
    int incl = g_scan[i] + g_boff[i >> 8];
    g_rowptr[i + 1] = incl;
    g_cursor[i] = incl - g_deg[i];           // exclusive start
    g_dinv[i] = rsqrtf((float)g_deg[i]);     // deg >= 1 always
    if (i == 0) g_rowptr[0] = 0;
}

__global__ void k_fill(const int* __restrict__ ei) {
    int i = blockIdx.x * blockDim.x + threadIdx.x;
    if (i >= EN) return;
    int s, d;
    if (i < EE) { s = ei[i]; d = ei[EE + i]; }
    else        { s = i - EE; d = s; }
    if ((unsigned)s >= NN || (unsigned)d >= NN) return;
    float w = g_dinv[s] * g_dinv[d];
    int pos = atomicAdd(&g_cursor[d], 1);
    g_edges[pos] = (long long)(unsigned)s |
                   ((long long)__float_as_uint(w) << 32);
}

// ---------------- GEMM1: g_relu = relu(x @ W1 + b1) -------------------------
// 128x128 tile, 256 threads, 8x8 per thread, packed f32x2 FMAs.
#define KC 16
__global__ void __launch_bounds__(256, 2)
k_gemm1(const float* __restrict__ A, const float* __restrict__ B,
        const float* __restrict__ bias) {
    __shared__ __align__(16) float As[KC][132];   // transposed A tile (k-major)
    __shared__ __align__(16) float Bs[KC][132];
    int tid  = threadIdx.x;
    int brow = blockIdx.y * 128;
    int bcol = blockIdx.x * 128;
    int tr = tid >> 4, tc = tid & 15;

    // A load: row = tid>>1, k-offset = (tid&1)*8 (two float4)
    int arow = tid >> 1;
    int ak   = (tid & 1) << 3;
    int grow = brow + arow;
    bool aok = grow < NN;
    const float* aptr = A + (size_t)grow * IND + ak;
    // B load: k-row = tid>>4, col-offset = (tid&15)*8
    int bk = tid >> 4;
    int bc = (tid & 15) << 3;
    const float* bptr = B + bk * HID + bcol + bc;

    float4 pa0, pa1, pb0, pb1;
    const float4 z4 = make_float4(0.f, 0.f, 0.f, 0.f);
    pa0 = aok ? *(const float4*)(aptr)     : z4;
    pa1 = aok ? *(const float4*)(aptr + 4) : z4;
    pb0 = *(const float4*)(bptr);
    pb1 = *(const float4*)(bptr + 4);

    u64 acc2[8][4];   // 8 rows x 4 col-pairs
    #pragma unroll
    for (int i = 0; i < 8; ++i)
        #pragma unroll
        for (int j = 0; j < 4; ++j) acc2[i][j] = 0ull;

    #pragma unroll 1
    for (int c = 0; c < IND / KC; ++c) {
        __syncthreads();
        As[ak + 0][arow] = pa0.x;
        As[ak + 1][arow] = pa0.y;
        As[ak + 2][arow] = pa0.z;
        As[ak + 3][arow] = pa0.w;
        As[ak + 4][arow] = pa1.x;
        As[ak + 5][arow] = pa1.y;
        As[ak + 6][arow] = pa1.z;
        As[ak + 7][arow] = pa1.w;
        *(float4*)&Bs[bk][bc]     = pb0;
        *(float4*)&Bs[bk][bc + 4] = pb1;
        __syncthreads();
        if (c + 1 < IND / KC) {
            const float* ap = aptr + (c + 1) * KC;
            pa0 = aok ? *(const float4*)(ap)     : z4;
            pa1 = aok ? *(const float4*)(ap + 4) : z4;
            const float* bp = bptr + (c + 1) * KC * HID;
            pb0 = *(const float4*)(bp);
            pb1 = *(const float4*)(bp + 4);
        }
        #pragma unroll
        for (int k = 0; k < KC; ++k) {
            float4 a0 = *(const float4*)&As[k][tr << 2];
            float4 a1 = *(const float4*)&As[k][64 + (tr << 2)];
            // B pairs straight out of LDS.128 register pairs (no repack)
            ulonglong2 bq0 = *(const ulonglong2*)&Bs[k][tc << 2];
            ulonglong2 bq1 = *(const ulonglong2*)&Bs[k][64 + (tc << 2)];
            u64 bp2[4] = {bq0.x, bq0.y, bq1.x, bq1.y};
            float av[8] = {a0.x, a0.y, a0.z, a0.w, a1.x, a1.y, a1.z, a1.w};
            #pragma unroll
            for (int i = 0; i < 8; ++i) {
                u64 aa;
                PACK_DUP(aa, av[i]);
                #pragma unroll
                for (int j = 0; j < 4; ++j) FMA2(acc2[i][j], aa, bp2[j]);
            }
        }
    }

    float4 bb0 = *(const float4*)(bias + bcol + (tc << 2));
    float4 bb1 = *(const float4*)(bias + bcol + 64 + (tc << 2));
    float bsv[8] = {bb0.x, bb0.y, bb0.z, bb0.w, bb1.x, bb1.y, bb1.z, bb1.w};
    #pragma unroll
    for (int half = 0; half < 2; ++half) {
        #pragma unroll
        for (int i = 0; i < 4; ++i) {
            int ii = half * 4 + i;
            int gr = brow + half * 64 + (tr << 2) + i;
            if (gr < NN) {
                float* orow = g_relu + (size_t)gr * HID + bcol;
                unsigned lo, hi;
                float v[8];
                #pragma unroll
                for (int j = 0; j < 4; ++j) {
                    UNPACK2(lo, hi, acc2[ii][j]);
                    v[2 * j]     = __uint_as_float(lo);
                    v[2 * j + 1] = __uint_as_float(hi);
                }
                float4 o0, o1;
                o0.x = fmaxf(v[0] + bsv[0], 0.f);
                o0.y = fmaxf(v[1] + bsv[1], 0.f);
                o0.z = fmaxf(v[2] + bsv[2], 0.f);
                o0.w = fmaxf(v[3] + bsv[3], 0.f);
                o1.x = fmaxf(v[4] + bsv[4], 0.f);
                o1.y = fmaxf(v[5] + bsv[5], 0.f);
                o1.z = fmaxf(v[6] + bsv[6], 0.f);
                o1.w = fmaxf(v[7] + bsv[7], 0.f);
                *(float4*)(orow + (tc << 2))      = o0;
                *(float4*)(orow + 64 + (tc << 2)) = o1;
            }
        }
    }
}

// ---------------- GEMM2: g_h = g_relu @ W2 + b2; seed r_K = temp[K]*h -------
// 256-row tile, 256 threads, 8 rows x 6 cols per thread, f32x2 FMAs.
#define G2KC 32
__global__ void __launch_bounds__(256)
k_gemm2(const float* __restrict__ W, const float* __restrict__ bias,
        const float* __restrict__ temp) {
    __shared__ __align__(16) float Ws[G2KC * 48];     // 6 KB
    __shared__ __align__(16) float As[G2KC * 260];    // k-major, pad 260
    int tid  = threadIdx.x;
    int row0 = blockIdx.x * 256;
    int rg = tid >> 3;    // 0..31 -> rows rg*8..rg*8+7
    int cg = tid & 7;     // cols cg*6..cg*6+5

    u64 acc2[8][3];
    #pragma unroll
    for (int i = 0; i < 8; ++i)
        #pragma unroll
        for (int j = 0; j < 3; ++j) acc2[i][j] = 0ull;

    for (int kb = 0; kb < HID; kb += G2KC) {
        __syncthreads();
        #pragma unroll
        for (int j = 0; j < 6; ++j) {
            int li = tid + j * 256;       // < 1536
            Ws[li] = W[kb * 48 + li];
        }
        #pragma unroll
        for (int j = 0; j < 8; ++j) {
            int f = tid + j * 256;        // < 2048
            int row = f >> 3;
            int q = f & 7;
            int gr = row0 + row;
            float4 v = (gr < NN) ? *(const float4*)(g_relu + (size_t)gr * HID + kb + q * 4)
                                 : make_float4(0.f, 0.f, 0.f, 0.f);
            As[(q * 4 + 0) * 260 + row] = v.x;
            As[(q * 4 + 1) * 260 + row] = v.y;
            As[(q * 4 + 2) * 260 + row] = v.z;
            As[(q * 4 + 3) * 260 + row] = v.w;
        }
        __syncthreads();
        #pragma unroll 4
        for (int k = 0; k < G2KC; ++k) {
            const float* wrow = Ws + k * 48 + cg * 6;
            u64 wp0 = *(const u64*)(wrow);
            u64 wp1 = *(const u64*)(wrow + 2);
            u64 wp2 = *(const u64*)(wrow + 4);
            float4 a0 = *(const float4*)&As[k * 260 + rg * 8];
            float4 a1 = *(const float4*)&As[k * 260 + rg * 8 + 4];
            float av[8] = {a0.x, a0.y, a0.z, a0.w, a1.x, a1.y, a1.z, a1.w};
            #pragma unroll
            for (int i = 0; i < 8; ++i) {
                u64 aa;
                PACK_DUP(aa, av[i]);
                FMA2(acc2[i][0], aa, wp0);
                FMA2(acc2[i][1], aa, wp1);
                FMA2(acc2[i][2], aa, wp2);
            }
        }
    }

    float tK = __ldg(temp + KHOP);     // (1-alpha)^K
    __half* rf = (__half*)g_rf0;
    float bs[6];
    #pragma unroll
    for (int j = 0; j < 6; ++j) bs[j] = bias[cg * 6 + j];
    #pragma unroll
    for (int i = 0; i < 8; ++i) {
        int gr = row0 + rg * 8 + i;
        if (gr < NN) {
            unsigned lo, hi;
            #pragma unroll
            for (int j = 0; j < 3; ++j) {
                UNPACK2(lo, hi, acc2[i][j]);
                float v0 = __uint_as_float(lo) + bs[2 * j];
                float v1 = __uint_as_float(hi) + bs[2 * j + 1];
                int c = cg * 6 + 2 * j;
                g_h[(size_t)gr * 48 + c]     = v0;
                g_h[(size_t)gr * 48 + c + 1] = v1;
                rf[(size_t)gr * 48 + c]     = __float2half_rn(tK * v0);
                rf[(size_t)gr * 48 + c + 1] = __float2half_rn(tK * v1);
            }
        }
    }
}

// ---------------- propagation (Horner): r_k = temp[k]*h + H r_{k+1} ---------
// 6 threads per node, uint4 (8 fp16) gathers: half the LDGs of the 12-thread
// variant at identical L2 data volume.
__global__ void k_prop(const float* __restrict__ temp, int k, int srcbuf,
                       float* __restrict__ out) {
    int t = blockIdx.x * blockDim.x + threadIdx.x;
    int node = t / 6;
    if (node >= NN) return;
    int fx = t - node * 6;

    const uint4* __restrict__ cur = srcbuf ? g_rf1 : g_rf0;
    uint4*       __restrict__ nxt = srcbuf ? g_rf0 : g_rf1;

    int beg = g_rowptr[node], end = g_rowptr[node + 1];
    float acc[8];
    #pragma unroll
    for (int i = 0; i < 8; ++i) acc[i] = 0.f;
    const int2* ed = (const int2*)g_edges;
    #pragma unroll 2
    for (int p = beg; p < end; ++p) {
        int2 e = ed[p];
        float w = __int_as_float(e.y);
        uint4 v = __ldg(&cur[e.x * 6 + fx]);
        float2 f0 = __half22float2(*reinterpret_cast<__half2*>(&v.x));
        float2 f1 = __half22float2(*reinterpret_cast<__half2*>(&v.y));
        float2 f2 = __half22float2(*reinterpret_cast<__half2*>(&v.z));
        float2 f3 = __half22float2(*reinterpret_cast<__half2*>(&v.w));
        acc[0] = fmaf(w, f0.x, acc[0]);
        acc[1] = fmaf(w, f0.y, acc[1]);
        acc[2] = fmaf(w, f1.x, acc[2]);
        acc[3] = fmaf(w, f1.y, acc[3]);
        acc[4] = fmaf(w, f2.x, acc[4]);
        acc[5] = fmaf(w, f2.y, acc[5]);
        acc[6] = fmaf(w, f3.x, acc[6]);
        acc[7] = fmaf(w, f3.y, acc[7]);
    }
    float g = __ldg(temp + k);
    const float* hrow = g_h + (size_t)node * 48 + fx * 8;
    float4 hv0 = *(const float4*)(hrow);
    float4 hv1 = *(const float4*)(hrow + 4);
    float r[8];
    r[0] = fmaf(g, hv0.x, acc[0]);
    r[1] = fmaf(g, hv0.y, acc[1]);
    r[2] = fmaf(g, hv0.z, acc[2]);
    r[3] = fmaf(g, hv0.w, acc[3]);
    r[4] = fmaf(g, hv1.x, acc[4]);
    r[5] = fmaf(g, hv1.y, acc[5]);
    r[6] = fmaf(g, hv1.z, acc[6]);
    r[7] = fmaf(g, hv1.w, acc[7]);
    if (k == 0) {
        float* orow = out + (size_t)node * 48 + fx * 8;
        *(float4*)(orow)     = make_float4(r[0], r[1], r[2], r[3]);
        *(float4*)(orow + 4) = make_float4(r[4], r[5], r[6], r[7]);
    } else {
        __half2 o0 = __floats2half2_rn(r[0], r[1]);
        __half2 o1 = __floats2half2_rn(r[2], r[3]);
        __half2 o2 = __floats2half2_rn(r[4], r[5]);
        __half2 o3 = __floats2half2_rn(r[6], r[7]);
        uint4 o;
        o.x = *reinterpret_cast<unsigned*>(&o0);
        o.y = *reinterpret_cast<unsigned*>(&o1);
        o.z = *reinterpret_cast<unsigned*>(&o2);
        o.w = *reinterpret_cast<unsigned*>(&o3);
        nxt[node * 6 + fx] = o;
    }
}

// ---------------- log_softmax (in place on d_out) ---------------------------
__global__ void k_lsm(float* __restrict__ out) {
    int gt = blockIdx.x * blockDim.x + threadIdx.x;
    int row = gt >> 5;
    int lane = gt & 31;
    if (row >= NN) return;
    float* r = out + (size_t)row * 48;
    float v0 = r[lane];
    float v1 = (lane < 16) ? r[32 + lane] : -3.4e38f;
    float m = fmaxf(v0, v1);
    #pragma unroll
    for (int s = 16; s; s >>= 1) m = fmaxf(m, __shfl_xor_sync(0xffffffffu, m, s));
    float e = expf(v0 - m) + ((lane < 16) ? expf(v1 - m) : 0.f);
    #pragma unroll
    for (int s = 16; s; s >>= 1) e += __shfl_xor_sync(0xffffffffu, e, s);
    float lse = m + logf(e);
    r[lane] = v0 - lse;
    if (lane < 16) r[32 + lane] = v1 - lse;
}

// ---------------- launch ----------------------------------------------------
extern "C" void kernel_launch(void* const* d_in, const int* in_sizes, int n_in,
                              void* d_out, int out_size) {
    const float* x    = (const float*)d_in[0];
    const int*   ei   = (const int*)d_in[1];      // int32 [2, EE]
    const float* W1   = (const float*)d_in[2];
    const float* b1   = (const float*)d_in[3];
    const float* W2   = (const float*)d_in[4];
    const float* b2   = (const float*)d_in[5];
    const float* temp = (const float*)d_in[6];
    float* out = (float*)d_out;
    (void)in_sizes; (void)n_in; (void)out_size;

    // k_gemm1 is launch #4 — the slot the fixed ncu window captures.
    k_init_deg<<<(NN + 255) / 256, 256>>>();              // 1
    k_count<<<(EE + 255) / 256, 256>>>(ei);               // 2
    k_scan1<<<NBS, 256>>>();                              // 3
    dim3 g1((HID + 127) / 128, (NN + 127) / 128);
    k_gemm1<<<g1, 256>>>(x, W1, b1);                      // 4  <- profiled
    k_scan2<<<1, 256>>>();                                // 5
    k_scan3<<<NBS, 256>>>();                              // 6
    k_fill<<<(EE + NN + 255) / 256, 256>>>(ei);           // 7
    k_gemm2<<<(NN + 255) / 256, 256>>>(W2, b2, temp);     // 8

    // Horner propagation: r_k = temp[k]*h + H r_{k+1}, k = K-1 .. 0
    for (int k = KHOP - 1; k >= 0; --k) {
        int s = KHOP - k;                       // step number 1..K
        int srcbuf = (s & 1) ? 0 : 1;           // r_{k+1} location
        k_prop<<<(NN * 6 + 191) / 192, 192>>>(temp, k, srcbuf, out);
    }

    k_lsm<<<(NN + 7) / 8, 256>>>(out);
}

// round 8
// speedup vs baseline: 1.0178x; 1.0178x over previous
#include <cuda_runtime.h>
#include <cuda_fp16.h>
#include <cstdint>

// Problem constants (fixed by the dataset)
#define NN   50000
#define EE   1600000
#define EN   1650000      // EE + NN self loops
#define IND  256
#define HID  256
#define OUTD 48
#define KHOP 10
#define NBS  196          // ceil(NN/256) scan blocks

typedef unsigned long long u64;

// Packed fp32x2 FMA: d = a*b + d (elementwise on 2 packed floats)
#define FMA2(acc, a, b) \
    asm("fma.rn.f32x2 %0, %1, %2, %0;" : "+l"(acc) : "l"(a), "l"(b))
#define PACK_DUP(out, f) do { \
    unsigned _u = __float_as_uint(f); \
    asm("mov.b64 %0, {%1, %1};" : "=l"(out) : "r"(_u)); \
} while (0)
#define UNPACK2(lo, hi, in) \
    asm("mov.b64 {%0, %1}, %2;" : "=r"(lo), "=r"(hi) : "l"(in))

// ---------------- scratch (device globals; no allocation allowed) ----------
__device__ float     g_relu[NN * HID];    // relu(x@W1+b1)
__device__ float     g_h[NN * OUTD];      // MLP output h (fp32)
__device__ uint2     g_rf0[NN * 12];      // fp16 r ping (48 halves per node)
__device__ uint2     g_rf1[NN * 12];      // fp16 r pong
__device__ int       g_deg[NN];
__device__ int       g_scan[NN];
__device__ int       g_bsum[256];
__device__ int       g_boff[256];
__device__ int       g_rowptr[NN + 1];
__device__ int       g_cursor[NN];
__device__ float     g_dinv[NN];
__device__ long long g_edges[EN];         // packed {src:int32 (lo), norm:f32 (hi)}

// ---------------- CSR build -------------------------------------------------
__global__ void k_init_deg() {
    int i = blockIdx.x * blockDim.x + threadIdx.x;
    if (i < NN) g_deg[i] = 1;   // self loop
}

__global__ void k_count(const int* __restrict__ ei) {
    int i = blockIdx.x * blockDim.x + threadIdx.x;
    if (i < EE) {
        int d = ei[EE + i];
        if ((unsigned)d < NN) atomicAdd(&g_deg[d], 1);
    }
}

__global__ void k_scan1() {
    __shared__ int s[256];
    int tx = threadIdx.x;
    int i = blockIdx.x * 256 + tx;
    int v = (i < NN) ? g_deg[i] : 0;
    s[tx] = v;
    __syncthreads();
    #pragma unroll
    for (int off = 1; off < 256; off <<= 1) {
        int add = (tx >= off) ? s[tx - off] : 0;
        __syncthreads();
        s[tx] += add;
        __syncthreads();
    }
    if (i < NN) g_scan[i] = s[tx];
    if (tx == 255) g_bsum[blockIdx.x] = s[255];
}

__global__ void k_scan2() {
    __shared__ int s[256];
    int tx = threadIdx.x;
    int v = (tx < NBS) ? g_bsum[tx] : 0;
    s[tx] = v;
    __syncthreads();
    #pragma unroll
    for (int off = 1; off < 256; off <<= 1) {
        int add = (tx >= off) ? s[tx - off] : 0;
        __syncthreads();
        s[tx] += add;
        __syncthreads();
    }
    g_boff[tx] = s[tx] - v;   // exclusive
}

__global__ void k_scan3() {
    int i = blockIdx.x * blockDim.x + threadIdx.x;
    if (i >= NN) return;
    int incl = g_scan[i] + g_boff[i >> 8];
    g_rowptr[i + 1] = incl;
    g_cursor[i] = incl - g_deg[i];           // exclusive start
    g_dinv[i] = rsqrtf((float)g_deg[i]);     // deg >= 1 always
    if (i == 0) g_rowptr[0] = 0;
}

__global__ void k_fill(const int* __restrict__ ei) {
    int i = blockIdx.x * blockDim.x + threadIdx.x;
    if (i >= EN) return;
    int s, d;
    if (i < EE) { s = ei[i]; d = ei[EE + i]; }
    else        { s = i - EE; d = s; }
    if ((unsigned)s >= NN || (unsigned)d >= NN) return;
    float w = g_dinv[s] * g_dinv[d];
    int pos = atomicAdd(&g_cursor[d], 1);
    g_edges[pos] = (long long)(unsigned)s |
                   ((long long)__float_as_uint(w) << 32);
}

// ---------------- GEMM1: g_relu = relu(x @ W1 + b1) -------------------------
// 128x128 tile, 256 threads, 8x8 per thread, packed f32x2 FMAs,
// double-buffered smem (one __syncthreads per k-chunk).
#define KC 16
__global__ void __launch_bounds__(256, 2)
k_gemm1(const float* __restrict__ A, const float* __restrict__ B,
        const float* __restrict__ bias) {
    __shared__ __align__(16) float As[2][KC][132];   // k-major A tiles
    __shared__ __align__(16) float Bs[2][KC][132];
    int tid  = threadIdx.x;
    int brow = blockIdx.y * 128;
    int bcol = blockIdx.x * 128;
    int tr = tid >> 4, tc = tid & 15;

    // A load: row = tid>>1, k-offset = (tid&1)*8 (two float4)
    int arow = tid >> 1;
    int ak   = (tid & 1) << 3;
    int grow = brow + arow;
    bool aok = grow < NN;
    const float* aptr = A + (size_t)grow * IND + ak;
    // B load: k-row = tid>>4, col-offset = (tid&15)*8
    int bk = tid >> 4;
    int bc = (tid & 15) << 3;
    const float* bptr = B + bk * HID + bcol + bc;

    float4 pa0, pa1, pb0, pb1;
    const float4 z4 = make_float4(0.f, 0.f, 0.f, 0.f);
    pa0 = aok ? *(const float4*)(aptr)     : z4;
    pa1 = aok ? *(const float4*)(aptr + 4) : z4;
    pb0 = *(const float4*)(bptr);
    pb1 = *(const float4*)(bptr + 4);

    u64 acc2[8][4];   // 8 rows x 4 col-pairs
    #pragma unroll
    for (int i = 0; i < 8; ++i)
        #pragma unroll
        for (int j = 0; j < 4; ++j) acc2[i][j] = 0ull;

    // Stage 0 fill
    As[0][ak + 0][arow] = pa0.x;
    As[0][ak + 1][arow] = pa0.y;
    As[0][ak + 2][arow] = pa0.z;
    As[0][ak + 3][arow] = pa0.w;
    As[0][ak + 4][arow] = pa1.x;
    As[0][ak + 5][arow] = pa1.y;
    As[0][ak + 6][arow] = pa1.z;
    As[0][ak + 7][arow] = pa1.w;
    *(float4*)&Bs[0][bk][bc]     = pb0;
    *(float4*)&Bs[0][bk][bc + 4] = pb1;
    __syncthreads();

    #pragma unroll 1
    for (int c = 0; c < IND / KC; ++c) {
        int cur = c & 1;
        if (c + 1 < IND / KC) {
            const float* ap = aptr + (c + 1) * KC;
            pa0 = aok ? *(const float4*)(ap)     : z4;
            pa1 = aok ? *(const float4*)(ap + 4) : z4;
            const float* bp = bptr + (c + 1) * KC * HID;
            pb0 = *(const float4*)(bp);
            pb1 = *(const float4*)(bp + 4);
        }
        #pragma unroll
        for (int k = 0; k < KC; ++k) {
            float4 a0 = *(const float4*)&As[cur][k][tr << 2];
            float4 a1 = *(const float4*)&As[cur][k][64 + (tr << 2)];
            // B pairs straight out of LDS.128 register pairs (no repack)
            ulonglong2 bq0 = *(const ulonglong2*)&Bs[cur][k][tc << 2];
            ulonglong2 bq1 = *(const ulonglong2*)&Bs[cur][k][64 + (tc << 2)];
            u64 bp2[4] = {bq0.x, bq0.y, bq1.x, bq1.y};
            float av[8] = {a0.x, a0.y, a0.z, a0.w, a1.x, a1.y, a1.z, a1.w};
            #pragma unroll
            for (int i = 0; i < 8; ++i) {
                u64 aa;
                PACK_DUP(aa, av[i]);
                #pragma unroll
                for (int j = 0; j < 4; ++j) FMA2(acc2[i][j], aa, bp2[j]);
            }
        }
        if (c + 1 < IND / KC) {
            int nxt = cur ^ 1;
            As[nxt][ak + 0][arow] = pa0.x;
            As[nxt][ak + 1][arow] = pa0.y;
            As[nxt][ak + 2][arow] = pa0.z;
            As[nxt][ak + 3][arow] = pa0.w;
            As[nxt][ak + 4][arow] = pa1.x;
            As[nxt][ak + 5][arow] = pa1.y;
            As[nxt][ak + 6][arow] = pa1.z;
            As[nxt][ak + 7][arow] = pa1.w;
            *(float4*)&Bs[nxt][bk][bc]     = pb0;
            *(float4*)&Bs[nxt][bk][bc + 4] = pb1;
            __syncthreads();
        }
    }

    float4 bb0 = *(const float4*)(bias + bcol + (tc << 2));
    float4 bb1 = *(const float4*)(bias + bcol + 64 + (tc << 2));
    float bsv[8] = {bb0.x, bb0.y, bb0.z, bb0.w, bb1.x, bb1.y, bb1.z, bb1.w};
    #pragma unroll
    for (int half = 0; half < 2; ++half) {
        #pragma unroll
        for (int i = 0; i < 4; ++i) {
            int ii = half * 4 + i;
            int gr = brow + half * 64 + (tr << 2) + i;
            if (gr < NN) {
                float* orow = g_relu + (size_t)gr * HID + bcol;
                unsigned lo, hi;
                float v[8];
                #pragma unroll
                for (int j = 0; j < 4; ++j) {
                    UNPACK2(lo, hi, acc2[ii][j]);
                    v[2 * j]     = __uint_as_float(lo);
                    v[2 * j + 1] = __uint_as_float(hi);
                }
                float4 o0, o1;
                o0.x = fmaxf(v[0] + bsv[0], 0.f);
                o0.y = fmaxf(v[1] + bsv[1], 0.f);
                o0.z = fmaxf(v[2] + bsv[2], 0.f);
                o0.w = fmaxf(v[3] + bsv[3], 0.f);
                o1.x = fmaxf(v[4] + bsv[4], 0.f);
                o1.y = fmaxf(v[5] + bsv[5], 0.f);
                o1.z = fmaxf(v[6] + bsv[6], 0.f);
                o1.w = fmaxf(v[7] + bsv[7], 0.f);
                *(float4*)(orow + (tc << 2))      = o0;
                *(float4*)(orow + 64 + (tc << 2)) = o1;
            }
        }
    }
}

// ---------------- GEMM2: g_h = g_relu @ W2 + b2; seed r_K = temp[K]*h -------
// 256-row tile, 256 threads, 8 rows x 6 cols per thread, f32x2 FMAs.
#define G2KC 32
__global__ void __launch_bounds__(256)
k_gemm2(const float* __restrict__ W, const float* __restrict__ bias,
        const float* __restrict__ temp) {
    __shared__ __align__(16) float Ws[G2KC * 48];     // 6 KB
    __shared__ __align__(16) float As[G2KC * 260];    // k-major, pad 260
    int tid  = threadIdx.x;
    int row0 = blockIdx.x * 256;
    int rg = tid >> 3;    // 0..31 -> rows rg*8..rg*8+7
    int cg = tid & 7;     // cols cg*6..cg*6+5

    u64 acc2[8][3];
    #pragma unroll
    for (int i = 0; i < 8; ++i)
        #pragma unroll
        for (int j = 0; j < 3; ++j) acc2[i][j] = 0ull;

    for (int kb = 0; kb < HID; kb += G2KC) {
        __syncthreads();
        #pragma unroll
        for (int j = 0; j < 6; ++j) {
            int li = tid + j * 256;       // < 1536
            Ws[li] = W[kb * 48 + li];
        }
        #pragma unroll
        for (int j = 0; j < 8; ++j) {
            int f = tid + j * 256;        // < 2048
            int row = f >> 3;
            int q = f & 7;
            int gr = row0 + row;
            float4 v = (gr < NN) ? *(const float4*)(g_relu + (size_t)gr * HID + kb + q * 4)
                                 : make_float4(0.f, 0.f, 0.f, 0.f);
            As[(q * 4 + 0) * 260 + row] = v.x;
            As[(q * 4 + 1) * 260 + row] = v.y;
            As[(q * 4 + 2) * 260 + row] = v.z;
            As[(q * 4 + 3) * 260 + row] = v.w;
        }
        __syncthreads();
        #pragma unroll 4
        for (int k = 0; k < G2KC; ++k) {
            const float* wrow = Ws + k * 48 + cg * 6;
            u64 wp0 = *(const u64*)(wrow);
            u64 wp1 = *(const u64*)(wrow + 2);
            u64 wp2 = *(const u64*)(wrow + 4);
            float4 a0 = *(const float4*)&As[k * 260 + rg * 8];
            float4 a1 = *(const float4*)&As[k * 260 + rg * 8 + 4];
            float av[8] = {a0.x, a0.y, a0.z, a0.w, a1.x, a1.y, a1.z, a1.w};
            #pragma unroll
            for (int i = 0; i < 8; ++i) {
                u64 aa;
                PACK_DUP(aa, av[i]);
                FMA2(acc2[i][0], aa, wp0);
                FMA2(acc2[i][1], aa, wp1);
                FMA2(acc2[i][2], aa, wp2);
            }
        }
    }

    float tK = __ldg(temp + KHOP);     // (1-alpha)^K
    __half* rf = (__half*)g_rf0;
    float bs[6];
    #pragma unroll
    for (int j = 0; j < 6; ++j) bs[j] = bias[cg * 6 + j];
    #pragma unroll
    for (int i = 0; i < 8; ++i) {
        int gr = row0 + rg * 8 + i;
        if (gr < NN) {
            unsigned lo, hi;
            #pragma unroll
            for (int j = 0; j < 3; ++j) {
                UNPACK2(lo, hi, acc2[i][j]);
                float v0 = __uint_as_float(lo) + bs[2 * j];
                float v1 = __uint_as_float(hi) + bs[2 * j + 1];
                int c = cg * 6 + 2 * j;
                g_h[(size_t)gr * 48 + c]     = v0;
                g_h[(size_t)gr * 48 + c + 1] = v1;
                rf[(size_t)gr * 48 + c]     = __float2half_rn(tK * v0);
                rf[(size_t)gr * 48 + c + 1] = __float2half_rn(tK * v1);
            }
        }
    }
}

// ---------------- propagation (Horner): r_k = temp[k]*h + H r_{k+1} ---------
// 12 threads per node, uint2 (4 fp16) gathers — max chip-wide MLP (R3-proven).
__global__ void k_prop(const float* __restrict__ temp, int k, int srcbuf,
                       float* __restrict__ out) {
    int t = blockIdx.x * blockDim.x + threadIdx.x;
    int node = t / 12;
    if (node >= NN) return;
    int fx = t - node * 12;

    const uint2* __restrict__ cur = srcbuf ? g_rf1 : g_rf0;
    uint2*       __restrict__ nxt = srcbuf ? g_rf0 : g_rf1;

    int beg = g_rowptr[node], end = g_rowptr[node + 1];
    float4 acc = make_float4(0.f, 0.f, 0.f, 0.f);
    const int2* ed = (const int2*)g_edges;
    #pragma unroll 4
    for (int p = beg; p < end; ++p) {
        int2 e = ed[p];
        float w = __int_as_float(e.y);
        uint2 v = __ldg(&cur[e.x * 12 + fx]);
        __half2 h0 = *reinterpret_cast<__half2*>(&v.x);
        __half2 h1 = *reinterpret_cast<__half2*>(&v.y);
        float2 f0 = __half22float2(h0);
        float2 f1 = __half22float2(h1);
        acc.x = fmaf(w, f0.x, acc.x);
        acc.y = fmaf(w, f0.y, acc.y);
        acc.z = fmaf(w, f1.x, acc.z);
        acc.w = fmaf(w, f1.y, acc.w);
    }
    float g = __ldg(temp + k);
    float4 hv = *(const float4*)(g_h + (size_t)node * 48 + fx * 4);
    float4 r;
    r.x = fmaf(g, hv.x, acc.x);
    r.y = fmaf(g, hv.y, acc.y);
    r.z = fmaf(g, hv.z, acc.z);
    r.w = fmaf(g, hv.w, acc.w);
    if (k == 0) {
        *(float4*)(out + (size_t)node * 48 + fx * 4) = r;
    } else {
        __half2 o0 = __floats2half2_rn(r.x, r.y);
        __half2 o1 = __floats2half2_rn(r.z, r.w);
        uint2 o;
        o.x = *reinterpret_cast<unsigned*>(&o0);
        o.y = *reinterpret_cast<unsigned*>(&o1);
        nxt[node * 12 + fx] = o;
    }
}

// ---------------- log_softmax (in place on d_out) ---------------------------
__global__ void k_lsm(float* __restrict__ out) {
    int gt = blockIdx.x * blockDim.x + threadIdx.x;
    int row = gt >> 5;
    int lane = gt & 31;
    if (row >= NN) return;
    float* r = out + (size_t)row * 48;
    float v0 = r[lane];
    float v1 = (lane < 16) ? r[32 + lane] : -3.4e38f;
    float m = fmaxf(v0, v1);
    #pragma unroll
    for (int s = 16; s; s >>= 1) m = fmaxf(m, __shfl_xor_sync(0xffffffffu, m, s));
    float e = expf(v0 - m) + ((lane < 16) ? expf(v1 - m) : 0.f);
    #pragma unroll
    for (int s = 16; s; s >>= 1) e += __shfl_xor_sync(0xffffffffu, e, s);
    float lse = m + logf(e);
    r[lane] = v0 - lse;
    if (lane < 16) r[32 + lane] = v1 - lse;
}

// ---------------- launch ----------------------------------------------------
extern "C" void kernel_launch(void* const* d_in, const int* in_sizes, int n_in,
                              void* d_out, int out_size) {
    const float* x    = (const float*)d_in[0];
    const int*   ei   = (const int*)d_in[1];      // int32 [2, EE]
    const float* W1   = (const float*)d_in[2];
    const float* b1   = (const float*)d_in[3];
    const float* W2   = (const float*)d_in[4];
    const float* b2   = (const float*)d_in[5];
    const float* temp = (const float*)d_in[6];
    float* out = (float*)d_out;
    (void)in_sizes; (void)n_in; (void)out_size;

    // k_gemm1 is launch #4 — the slot the fixed ncu window captures.
    k_init_deg<<<(NN + 255) / 256, 256>>>();              // 1
    k_count<<<(EE + 255) / 256, 256>>>(ei);               // 2
    k_scan1<<<NBS, 256>>>();                              // 3
    dim3 g1((HID + 127) / 128, (NN + 127) / 128);
    k_gemm1<<<g1, 256>>>(x, W1, b1);                      // 4  <- profiled
    k_scan2<<<1, 256>>>();                                // 5
    k_scan3<<<NBS, 256>>>();                              // 6
    k_fill<<<(EE + NN + 255) / 256, 256>>>(ei);           // 7
    k_gemm2<<<(NN + 255) / 256, 256>>>(W2, b2, temp);     // 8

    // Horner propagation: r_k = temp[k]*h + H r_{k+1}, k = K-1 .. 0
    for (int k = KHOP - 1; k >= 0; --k) {
        int s = KHOP - k;                       // step number 1..K
        int srcbuf = (s & 1) ? 0 : 1;           // r_{k+1} location
        k_prop<<<(NN * 12 + 191) / 192, 192>>>(temp, k, srcbuf, out);
    }

    k_lsm<<<(NN + 7) / 8, 256>>>(out);
}